// round 1
// baseline (speedup 1.0000x reference)
#include <cuda_runtime.h>
#include <math.h>

// Problem constants
#define BB 4
#define NN 4096
#define DD 64
#define SIGMA 0.005f
#define INV_S2 40000.0f          // 1/SIGMA^2
#define SHIFT 64.0f              // fixed log-sum-exp shift for feature logits (fd <= 0, row max > -150 for this data)

#define ROWS 128                 // rows per CTA (one per thread in each half)
#define MT 64                    // column tile size
#define NSPLIT 2                 // column splits per CTA (two halves of the block)
#define THREADS (ROWS * NSPLIT)  // 256
#define TILES_PER_SPLIT (NN / MT / NSPLIT)   // 32

// Scratch: per-row squared norms of pointfea2 (allowed __device__ global scratch)
__device__ float g_n2[BB * NN];

// ---------------------------------------------------------------------------
// Zero the 8 output floats (ce_loss[4], reg[4]) each replay
// ---------------------------------------------------------------------------
__global__ void init_kernel(float* out) {
    if (threadIdx.x < 8) out[threadIdx.x] = 0.0f;
}

// ---------------------------------------------------------------------------
// Precompute ||f2_m||^2 for every row (B*N rows of 64)
// ---------------------------------------------------------------------------
__global__ void norm_kernel(const float* __restrict__ f2) {
    int i = blockIdx.x * blockDim.x + threadIdx.x;   // row id over B*N
    if (i >= BB * NN) return;
    const float4* v = (const float4*)(f2 + (size_t)i * DD);
    float s = 0.0f;
#pragma unroll
    for (int j = 0; j < DD / 4; j++) {
        float4 x = v[j];
        s = fmaf(x.x, x.x, s);
        s = fmaf(x.y, x.y, s);
        s = fmaf(x.z, x.z, s);
        s = fmaf(x.w, x.w, s);
    }
    g_n2[i] = s;
}

// ---------------------------------------------------------------------------
// Fused cross-entropy kernel.
// CTA = (row_tile, batch). 256 threads = 128 rows x 2 column-splits.
// Each thread owns one row n, keeps f1 row in registers, streams f2 column
// tiles through shared memory, maintaining:
//   ZPD = sum_m exp(pd)          (pd <= 0, max is exactly 0 on diagonal)
//   TPD = sum_m exp(pd) * fd
//   ZFD = sum_m exp(fd + SHIFT)
// Then ce_n = (log(ZFD) - SHIFT) - TPD/ZPD, and ce_loss[b] = sum_n w_n ce_n.
// ---------------------------------------------------------------------------
__global__ void __launch_bounds__(THREADS, 1)
ce_kernel(const float* __restrict__ points,
          const float* __restrict__ f1,
          const float* __restrict__ f2,
          const float* __restrict__ w,
          float* __restrict__ out)
{
    __shared__ float  f2s[NSPLIT][MT][DD];   // 2 * 64 * 64 * 4 = 32 KB
    __shared__ float4 pts[NSPLIT][MT];       // (x, y, z, ||f2_m||^2)
    __shared__ float  wsum[8];

    const int b    = blockIdx.y;
    const int half = threadIdx.x >> 7;       // 0 or 1 (column split)
    const int r    = threadIdx.x & 127;      // row within tile
    const int n    = blockIdx.x * ROWS + r;  // global row

    // Load f1 row into registers + its squared norm
    float a[DD];
    float n1 = 0.0f;
    const float4* f1v = (const float4*)(f1 + ((size_t)(b * NN + n)) * DD);
#pragma unroll
    for (int j = 0; j < DD / 4; j++) {
        float4 v = f1v[j];
        a[4 * j + 0] = v.x; a[4 * j + 1] = v.y;
        a[4 * j + 2] = v.z; a[4 * j + 3] = v.w;
        n1 = fmaf(v.x, v.x, n1); n1 = fmaf(v.y, v.y, n1);
        n1 = fmaf(v.z, v.z, n1); n1 = fmaf(v.w, v.w, n1);
    }
    const float px = points[(b * NN + n) * 3 + 0];
    const float py = points[(b * NN + n) * 3 + 1];
    const float pz = points[(b * NN + n) * 3 + 2];

    float ZPD = 0.0f, TPD = 0.0f, ZFD = 0.0f;

    for (int t = 0; t < TILES_PER_SPLIT; t++) {
        const int m0 = (half * TILES_PER_SPLIT + t) * MT;

        // Cooperative tile load (each half loads its own tile, coalesced)
        {
            const float4* src = (const float4*)(f2 + ((size_t)(b * NN + m0)) * DD);
            float4* dst = (float4*)&f2s[half][0][0];
#pragma unroll
            for (int j = 0; j < (MT * DD / 4) / ROWS; j++)   // 8 float4 per thread
                dst[r + j * ROWS] = src[r + j * ROWS];
            if (r < MT) {
                const float* pp = points + ((size_t)(b * NN + m0)) * 3;
                float4 pv;
                pv.x = pp[r * 3 + 0];
                pv.y = pp[r * 3 + 1];
                pv.z = pp[r * 3 + 2];
                pv.w = g_n2[b * NN + m0 + r];
                pts[half][r] = pv;
            }
        }
        __syncthreads();

#pragma unroll 2
        for (int m = 0; m < MT; m++) {
            const float4* fv = (const float4*)&f2s[half][m][0];
            float d0 = 0.0f, d1 = 0.0f, d2 = 0.0f, d3 = 0.0f;
#pragma unroll
            for (int j = 0; j < DD / 4; j += 4) {
                float4 v0 = fv[j + 0], v1 = fv[j + 1], v2 = fv[j + 2], v3 = fv[j + 3];
                d0 = fmaf(a[4 * j + 0],  v0.x, d0);
                d0 = fmaf(a[4 * j + 1],  v0.y, d0);
                d0 = fmaf(a[4 * j + 2],  v0.z, d0);
                d0 = fmaf(a[4 * j + 3],  v0.w, d0);
                d1 = fmaf(a[4 * j + 4],  v1.x, d1);
                d1 = fmaf(a[4 * j + 5],  v1.y, d1);
                d1 = fmaf(a[4 * j + 6],  v1.z, d1);
                d1 = fmaf(a[4 * j + 7],  v1.w, d1);
                d2 = fmaf(a[4 * j + 8],  v2.x, d2);
                d2 = fmaf(a[4 * j + 9],  v2.y, d2);
                d2 = fmaf(a[4 * j + 10], v2.z, d2);
                d2 = fmaf(a[4 * j + 11], v2.w, d2);
                d3 = fmaf(a[4 * j + 12], v3.x, d3);
                d3 = fmaf(a[4 * j + 13], v3.y, d3);
                d3 = fmaf(a[4 * j + 14], v3.z, d3);
                d3 = fmaf(a[4 * j + 15], v3.w, d3);
            }
            const float dot = (d0 + d1) + (d2 + d3);
            const float4 pm = pts[half][m];
            const float fd = 2.0f * dot - n1 - pm.w;        // feature logit (<= ~0)
            const float dx = px - pm.x, dy = py - pm.y, dz = pz - pm.z;
            const float pd = fmaf(dx, dx, fmaf(dy, dy, dz * dz)) * (-INV_S2);
            const float epd = __expf(pd);                   // max is exactly 0 (diag)
            ZPD += epd;
            TPD = fmaf(epd, fd, TPD);
            ZFD += __expf(fd + SHIFT);
        }
        __syncthreads();
    }

    // Combine the two column halves (all sums plainly additive: fixed shifts)
    float* red = &f2s[0][0][0];
    if (half == 1) {
        red[r]       = ZPD;
        red[128 + r] = TPD;
        red[256 + r] = ZFD;
    }
    __syncthreads();
    float val = 0.0f;
    if (half == 0) {
        ZPD += red[r];
        TPD += red[128 + r];
        ZFD += red[256 + r];
        const float ce = (logf(ZFD) - SHIFT) - TPD / ZPD;
        val = w[b * NN + n] * ce;
    }
    __syncthreads();

    // Block reduction of val (half 1 contributes zeros)
#pragma unroll
    for (int o = 16; o > 0; o >>= 1)
        val += __shfl_down_sync(0xffffffffu, val, o);
    if ((threadIdx.x & 31) == 0) wsum[threadIdx.x >> 5] = val;
    __syncthreads();
    if (threadIdx.x < 8) {
        float v = wsum[threadIdx.x];
        v += __shfl_down_sync(0xffu, v, 4);
        v += __shfl_down_sync(0xffu, v, 2);
        v += __shfl_down_sync(0xffu, v, 1);
        if (threadIdx.x == 0) atomicAdd(&out[b], v);
    }
}

// ---------------------------------------------------------------------------
// reg[b] = mean_n mean_d (f1^2 + f2^2)
// ---------------------------------------------------------------------------
__global__ void reg_kernel(const float* __restrict__ f1,
                           const float* __restrict__ f2,
                           float* __restrict__ out)
{
    __shared__ float wsum[8];
    const int b = blockIdx.y;
    const int nchunks = gridDim.x;
    const int total4 = NN * DD / 4;                  // 65536 float4 per batch
    const int chunk = total4 / nchunks;
    const int start = blockIdx.x * chunk;
    const float4* x = (const float4*)f1 + (size_t)b * total4;
    const float4* y = (const float4*)f2 + (size_t)b * total4;

    float s = 0.0f;
    for (int i = start + threadIdx.x; i < start + chunk; i += blockDim.x) {
        float4 u = x[i];
        s = fmaf(u.x, u.x, s); s = fmaf(u.y, u.y, s);
        s = fmaf(u.z, u.z, s); s = fmaf(u.w, u.w, s);
        float4 v = y[i];
        s = fmaf(v.x, v.x, s); s = fmaf(v.y, v.y, s);
        s = fmaf(v.z, v.z, s); s = fmaf(v.w, v.w, s);
    }
#pragma unroll
    for (int o = 16; o > 0; o >>= 1)
        s += __shfl_down_sync(0xffffffffu, s, o);
    if ((threadIdx.x & 31) == 0) wsum[threadIdx.x >> 5] = s;
    __syncthreads();
    if (threadIdx.x < 8) {
        float v = wsum[threadIdx.x];
        v += __shfl_down_sync(0xffu, v, 4);
        v += __shfl_down_sync(0xffu, v, 2);
        v += __shfl_down_sync(0xffu, v, 1);
        if (threadIdx.x == 0)
            atomicAdd(&out[4 + b], v * (1.0f / (float)(NN * DD)));
    }
}

// ---------------------------------------------------------------------------
extern "C" void kernel_launch(void* const* d_in, const int* in_sizes, int n_in,
                              void* d_out, int out_size)
{
    const float* points = (const float*)d_in[0];
    const float* f1     = (const float*)d_in[1];
    const float* f2     = (const float*)d_in[2];
    const float* w      = (const float*)d_in[3];
    float* out          = (float*)d_out;

    init_kernel<<<1, 32>>>(out);
    norm_kernel<<<(BB * NN + 255) / 256, 256>>>(f2);
    ce_kernel<<<dim3(NN / ROWS, BB), THREADS>>>(points, f1, f2, w, out);
    reg_kernel<<<dim3(8, BB), 256>>>(f1, f2, out);
}

// round 3
// speedup vs baseline: 2.9559x; 2.9559x over previous
#include <cuda_runtime.h>
#include <cuda_bf16.h>
#include <math.h>
#include <stdint.h>

#define BB 4
#define NN 4096
#define DD 64
#define SHIFT 64.0f
#define L2E 1.4426950408889634f
#define SHL2E (SHIFT * L2E)
#define NGL2E (-40000.0f * L2E)       /* -(1/sigma^2)*log2(e) */
#define STH 0.00226f                  /* dist^2 beyond which exp2 underflows to 0 */

#define ROWS 128
#define CT 128
#define T_TILES (NN / CT)             /* 32 */
#define THREADS 256

/* ---- SMEM layout (bytes) ---- */
#define OFF_AHI  0
#define OFF_ALO  16384
#define OFF_BHI  32768                /* + bf*32768 ; BLO at +16384 */
#define OFF_COLC 98304                /* 2 bufs * 2048 */
#define OFF_WSUM 102400
#define SMEM_TOTAL 102528

/* ---- device scratch (blocked, swizzled bf16 hi/lo tiles) ---- */
__device__ __align__(16) unsigned char g_f1hi[BB * NN * 128];
__device__ __align__(16) unsigned char g_f1lo[BB * NN * 128];
__device__ __align__(16) unsigned char g_f2hi[BB * NN * 128];
__device__ __align__(16) unsigned char g_f2lo[BB * NN * 128];
__device__ float g_colc[BB * T_TILES * 4 * 128];   /* qx,qy,qz,n2 SoA per tile */
__device__ float g_n1[BB * NN];

/* ------------------------------- asm helpers ----------------------------- */
__device__ __forceinline__ uint32_t smem_u32(const void* p) {
    uint32_t a;
    asm("{ .reg .u64 t; cvta.to.shared.u64 t, %1; cvt.u32.u64 %0, t; }" : "=r"(a) : "l"(p));
    return a;
}
__device__ __forceinline__ float ex2_(float x) {
    float r;
    asm("ex2.approx.ftz.f32 %0, %1;" : "=f"(r) : "f"(x));
    return r;
}
#define CPA16(dst, src) \
    asm volatile("cp.async.cg.shared.global [%0], [%1], 16;" :: "r"(dst), "l"(src))
#define CPA_COMMIT() asm volatile("cp.async.commit_group;" ::: "memory")
#define CPA_WAIT0()  asm volatile("cp.async.wait_group 0;" ::: "memory")

#define LDSM4(r, addr) \
    asm volatile("ldmatrix.sync.aligned.m8n8.x4.shared.b16 {%0,%1,%2,%3}, [%4];" \
        : "=r"((r)[0]), "=r"((r)[1]), "=r"((r)[2]), "=r"((r)[3]) : "r"(addr))

#define MMA16816(c, a, b0_, b1_) \
    asm volatile("mma.sync.aligned.m16n8k16.row.col.f32.bf16.bf16.f32 " \
        "{%0,%1,%2,%3},{%4,%5,%6,%7},{%8,%9},{%0,%1,%2,%3};" \
        : "+f"((c)[0]), "+f"((c)[1]), "+f"((c)[2]), "+f"((c)[3]) \
        : "r"((a)[0]), "r"((a)[1]), "r"((a)[2]), "r"((a)[3]), "r"(b0_), "r"(b1_))

/* ------------------------------- prep kernel ----------------------------- */
/* Per thread = one row of f1 and f2: write blocked swizzled hi/lo bf16 tiles,
   norms, packed column constants, and the reg loss. */
__device__ __forceinline__ void cvt8(const float* f, uint4& hi, uint4& lo) {
    uint32_t h[4], l[4];
#pragma unroll
    for (int i = 0; i < 4; i++) {
        float a = f[2 * i], b = f[2 * i + 1];
        __nv_bfloat162 hh = __floats2bfloat162_rn(a, b);
        __nv_bfloat162 ll = __floats2bfloat162_rn(a - __bfloat162float(hh.x),
                                                  b - __bfloat162float(hh.y));
        h[i] = *reinterpret_cast<uint32_t*>(&hh);
        l[i] = *reinterpret_cast<uint32_t*>(&ll);
    }
    hi = make_uint4(h[0], h[1], h[2], h[3]);
    lo = make_uint4(l[0], l[1], l[2], l[3]);
}

__global__ void __launch_bounds__(256)
prep_kernel(const float* __restrict__ points,
            const float* __restrict__ f1,
            const float* __restrict__ f2,
            float* __restrict__ out)
{
    __shared__ float wsum[8];
    const int tid = threadIdx.x;
    const int row = blockIdx.x * 256 + tid;        /* 0 .. B*NN-1 */
    const int b = row >> 12, n = row & (NN - 1);
    const int t = n >> 7, rin = n & 127;
    const size_t tb = ((size_t)(b * T_TILES + t)) * 16384 + (size_t)rin * 128;
    const int sw = rin & 7;

    float f[DD];
    float n1 = 0.f, n2 = 0.f;
    {
        const float4* v = (const float4*)(f1 + (size_t)row * DD);
#pragma unroll
        for (int j = 0; j < DD / 4; j++) {
            float4 x = v[j];
            f[4 * j] = x.x; f[4 * j + 1] = x.y; f[4 * j + 2] = x.z; f[4 * j + 3] = x.w;
            n1 = fmaf(x.x, x.x, n1); n1 = fmaf(x.y, x.y, n1);
            n1 = fmaf(x.z, x.z, n1); n1 = fmaf(x.w, x.w, n1);
        }
#pragma unroll
        for (int c = 0; c < 8; c++) {
            uint4 hi, lo;
            cvt8(f + 8 * c, hi, lo);
            const size_t off = tb + (size_t)(((c ^ sw) << 4));
            *reinterpret_cast<uint4*>(g_f1hi + off) = hi;
            *reinterpret_cast<uint4*>(g_f1lo + off) = lo;
        }
    }
    {
        const float4* v = (const float4*)(f2 + (size_t)row * DD);
#pragma unroll
        for (int j = 0; j < DD / 4; j++) {
            float4 x = v[j];
            f[4 * j] = x.x; f[4 * j + 1] = x.y; f[4 * j + 2] = x.z; f[4 * j + 3] = x.w;
            n2 = fmaf(x.x, x.x, n2); n2 = fmaf(x.y, x.y, n2);
            n2 = fmaf(x.z, x.z, n2); n2 = fmaf(x.w, x.w, n2);
        }
#pragma unroll
        for (int c = 0; c < 8; c++) {
            uint4 hi, lo;
            cvt8(f + 8 * c, hi, lo);
            const size_t off = tb + (size_t)(((c ^ sw) << 4));
            *reinterpret_cast<uint4*>(g_f2hi + off) = hi;
            *reinterpret_cast<uint4*>(g_f2lo + off) = lo;
        }
    }
    g_n1[row] = n1;
    const int cbase = (b * T_TILES + t) * 512;
    g_colc[cbase + rin]       = points[(size_t)row * 3 + 0];
    g_colc[cbase + 128 + rin] = points[(size_t)row * 3 + 1];
    g_colc[cbase + 256 + rin] = points[(size_t)row * 3 + 2];
    g_colc[cbase + 384 + rin] = n2;

    /* reg loss */
    float s = n1 + n2;
#pragma unroll
    for (int o = 16; o > 0; o >>= 1) s += __shfl_down_sync(0xffffffffu, s, o);
    if ((tid & 31) == 0) wsum[tid >> 5] = s;
    __syncthreads();
    if (tid < 8) {
        float v = wsum[tid];
        v += __shfl_down_sync(0xffu, v, 4);
        v += __shfl_down_sync(0xffu, v, 2);
        v += __shfl_down_sync(0xffu, v, 1);
        if (tid == 0) atomicAdd(&out[4 + b], v * (1.0f / (float)(NN * DD)));
    }
}

__global__ void init_kernel(float* out) {
    if (threadIdx.x < 8) out[threadIdx.x] = 0.0f;
}

/* ----------------------------- epilogue helper --------------------------- */
__device__ __forceinline__ void row_epi(
    float d0, float d1, float d2, float d3,
    const float* qxv, const float* qyv, const float* qzv, const float* n2v,
    float px, float py, float pz, float n1,
    float& zpd, float& tpd, float& zfd)
{
    float dv[4] = { d0, d1, d2, d3 };
    float fd[4], sv[4];
    float smin = 1e30f;
#pragma unroll
    for (int c = 0; c < 4; c++) {
        float dx = qxv[c] - px, dy = qyv[c] - py, dz = qzv[c] - pz;
        float s = fmaf(dx, dx, fmaf(dy, dy, dz * dz));
        sv[c] = s;
        smin = fminf(smin, s);
        float fdl = fmaf(2.0f, dv[c], -(n1 + n2v[c]));
        fd[c] = fdl;
        zfd += ex2_(fmaf(fdl, L2E, SHL2E));
    }
    if (smin < STH) {
#pragma unroll
        for (int c = 0; c < 4; c++) {
            float e = ex2_(sv[c] * NGL2E);
            zpd += e;
            tpd = fmaf(e, fd[c], tpd);
        }
    }
}

/* -------------------------------- ce kernel ------------------------------ */
__global__ void __launch_bounds__(THREADS, 1)
ce_kernel(const float* __restrict__ points,
          const float* __restrict__ w,
          float* __restrict__ out)
{
    extern __shared__ char sm[];
    const uint32_t smb = smem_u32(sm);
    const int tid = threadIdx.x;
    const int wid = tid >> 5, lane = tid & 31;
    const int b = blockIdx.y, bx = blockIdx.x;

    /* ---- prologue cp.async: A tiles + B tile 0 + colc 0 ---- */
    {
        const size_t abase = ((size_t)(b * T_TILES + bx)) * 16384;
#pragma unroll
        for (int j = 0; j < 4; j++) {
            const uint32_t c16 = (uint32_t)(tid + j * 256) * 16;
            CPA16(smb + OFF_AHI + c16, g_f1hi + abase + c16);
            CPA16(smb + OFF_ALO + c16, g_f1lo + abase + c16);
        }
        const size_t bbase = ((size_t)(b * T_TILES + 0)) * 16384;
#pragma unroll
        for (int j = 0; j < 4; j++) {
            const uint32_t c16 = (uint32_t)(tid + j * 256) * 16;
            CPA16(smb + OFF_BHI + c16, g_f2hi + bbase + c16);
            CPA16(smb + OFF_BHI + 16384 + c16, g_f2lo + bbase + c16);
        }
        if (tid < 128) {
            const uint32_t c16 = (uint32_t)tid * 16;
            CPA16(smb + OFF_COLC + c16,
                  (const char*)(g_colc + (size_t)(b * T_TILES) * 512) + c16);
        }
        CPA_COMMIT();
    }

    /* ---- per-thread row constants ---- */
    const int q = lane & 3;
    const int kq = lane >> 2;
    const int r0 = wid * 16 + kq;               /* local rows r0, r0+8 */
    const int n0 = bx * ROWS + r0;
    const float n1a = g_n1[b * NN + n0];
    const float n1b = g_n1[b * NN + n0 + 8];
    const float pxa = points[((size_t)(b * NN + n0)) * 3 + 0];
    const float pya = points[((size_t)(b * NN + n0)) * 3 + 1];
    const float pza = points[((size_t)(b * NN + n0)) * 3 + 2];
    const float pxb = points[((size_t)(b * NN + n0 + 8)) * 3 + 0];
    const float pyb = points[((size_t)(b * NN + n0 + 8)) * 3 + 1];
    const float pzb = points[((size_t)(b * NN + n0 + 8)) * 3 + 2];

    CPA_WAIT0();
    __syncthreads();

    /* ---- load persistent A fragments ---- */
    const int g = lane >> 3, li = lane & 7;
    const int gh = g >> 1;
    uint32_t aH[4][4], aL[4][4];
    {
        const int rA = wid * 16 + (g & 1) * 8 + li;
        const uint32_t abH = smb + OFF_AHI + rA * 128;
        const uint32_t abL = smb + OFF_ALO + rA * 128;
        const int sA = rA & 7;
#pragma unroll
        for (int kc = 0; kc < 4; kc++) {
            const uint32_t off = (uint32_t)(((2 * kc + gh) ^ sA) << 4);
            LDSM4(aH[kc], abH + off);
            LDSM4(aL[kc], abL + off);
        }
    }
    const int rl = (g & 1) * 8 + li;            /* B-fragment row-in-colpair */
    const int sB = rl & 7;

    float zpd0 = 0.f, tpd0 = 0.f, zfd0 = 0.f;
    float zpd1 = 0.f, tpd1 = 0.f, zfd1 = 0.f;

    for (int t = 0; t < T_TILES; t++) {
        const int bf = t & 1;
        /* issue next tile */
        if (t + 1 < T_TILES) {
            const int nbf = bf ^ 1;
            const size_t bbase = ((size_t)(b * T_TILES + t + 1)) * 16384;
            const uint32_t dstB = smb + OFF_BHI + nbf * 32768;
#pragma unroll
            for (int j = 0; j < 4; j++) {
                const uint32_t c16 = (uint32_t)(tid + j * 256) * 16;
                CPA16(dstB + c16, g_f2hi + bbase + c16);
                CPA16(dstB + 16384 + c16, g_f2lo + bbase + c16);
            }
            if (tid < 128) {
                const uint32_t c16 = (uint32_t)tid * 16;
                CPA16(smb + OFF_COLC + nbf * 2048 + c16,
                      (const char*)(g_colc + (size_t)(b * T_TILES + t + 1) * 512) + c16);
            }
            CPA_COMMIT();
        }

        const float* colcp = (const float*)(sm + OFF_COLC + bf * 2048);
        const uint32_t bbufH = smb + OFF_BHI + bf * 32768;
        const uint32_t bbufL = bbufH + 16384;

#pragma unroll 1
        for (int cp = 0; cp < 8; cp++) {
            /* B fragments for this 16-column pair */
            uint32_t bh[4][4], bl[4][4];
            const uint32_t bbH = bbufH + cp * 2048 + rl * 128;
            const uint32_t bbL = bbufL + cp * 2048 + rl * 128;
#pragma unroll
            for (int kc = 0; kc < 4; kc++) {
                const uint32_t off = (uint32_t)(((2 * kc + gh) ^ sB) << 4);
                LDSM4(bh[kc], bbH + off);
                LDSM4(bl[kc], bbL + off);
            }
            float accA[4] = {0.f, 0.f, 0.f, 0.f};
            float accB[4] = {0.f, 0.f, 0.f, 0.f};
#pragma unroll
            for (int kc = 0; kc < 4; kc++) {
                MMA16816(accA, aH[kc], bh[kc][0], bh[kc][2]);
                MMA16816(accB, aH[kc], bh[kc][1], bh[kc][3]);
            }
#pragma unroll
            for (int kc = 0; kc < 4; kc++) {
                MMA16816(accA, aH[kc], bl[kc][0], bl[kc][2]);
                MMA16816(accB, aH[kc], bl[kc][1], bl[kc][3]);
            }
#pragma unroll
            for (int kc = 0; kc < 4; kc++) {
                MMA16816(accA, aL[kc], bh[kc][0], bh[kc][2]);
                MMA16816(accB, aL[kc], bh[kc][1], bh[kc][3]);
            }

            /* epilogue for 8 elements (2 rows x 4 cols) */
            const int lc0 = cp * 16 + 2 * q;
            const int lc1 = lc0 + 8;
            float2 x0 = *(const float2*)(colcp + lc0);
            float2 x1 = *(const float2*)(colcp + lc1);
            float2 y0 = *(const float2*)(colcp + 128 + lc0);
            float2 y1 = *(const float2*)(colcp + 128 + lc1);
            float2 z0 = *(const float2*)(colcp + 256 + lc0);
            float2 z1 = *(const float2*)(colcp + 256 + lc1);
            float2 m0 = *(const float2*)(colcp + 384 + lc0);
            float2 m1 = *(const float2*)(colcp + 384 + lc1);
            const float qxv[4] = { x0.x, x0.y, x1.x, x1.y };
            const float qyv[4] = { y0.x, y0.y, y1.x, y1.y };
            const float qzv[4] = { z0.x, z0.y, z1.x, z1.y };
            const float n2v[4] = { m0.x, m0.y, m1.x, m1.y };

            row_epi(accA[0], accA[1], accB[0], accB[1],
                    qxv, qyv, qzv, n2v, pxa, pya, pza, n1a, zpd0, tpd0, zfd0);
            row_epi(accA[2], accA[3], accB[2], accB[3],
                    qxv, qyv, qzv, n2v, pxb, pyb, pzb, n1b, zpd1, tpd1, zfd1);
        }

        if (t + 1 < T_TILES) CPA_WAIT0();
        __syncthreads();
    }

    /* ---- reduce across the 4 lanes of each quad (cols) ---- */
#pragma unroll
    for (int o = 1; o <= 2; o <<= 1) {
        zpd0 += __shfl_xor_sync(0xffffffffu, zpd0, o);
        tpd0 += __shfl_xor_sync(0xffffffffu, tpd0, o);
        zfd0 += __shfl_xor_sync(0xffffffffu, zfd0, o);
        zpd1 += __shfl_xor_sync(0xffffffffu, zpd1, o);
        tpd1 += __shfl_xor_sync(0xffffffffu, tpd1, o);
        zfd1 += __shfl_xor_sync(0xffffffffu, zfd1, o);
    }
    float val = 0.f;
    if (q == 0) {
        const float ce0 = (logf(zfd0) - SHIFT) - tpd0 / zpd0;
        const float ce1 = (logf(zfd1) - SHIFT) - tpd1 / zpd1;
        val = w[b * NN + n0] * ce0 + w[b * NN + n0 + 8] * ce1;
    }
#pragma unroll
    for (int o = 16; o > 0; o >>= 1) val += __shfl_down_sync(0xffffffffu, val, o);
    float* wsum = (float*)(sm + OFF_WSUM);
    if (lane == 0) wsum[wid] = val;
    __syncthreads();
    if (tid < 8) {
        float v = wsum[tid];
        v += __shfl_down_sync(0xffu, v, 4);
        v += __shfl_down_sync(0xffu, v, 2);
        v += __shfl_down_sync(0xffu, v, 1);
        if (tid == 0) atomicAdd(&out[b], v);
    }
}

/* -------------------------------- launcher ------------------------------- */
extern "C" void kernel_launch(void* const* d_in, const int* in_sizes, int n_in,
                              void* d_out, int out_size)
{
    const float* points = (const float*)d_in[0];
    const float* f1     = (const float*)d_in[1];
    const float* f2     = (const float*)d_in[2];
    const float* w      = (const float*)d_in[3];
    float* out          = (float*)d_out;

    static bool attr_set = false;
    if (!attr_set) {
        cudaFuncSetAttribute(ce_kernel, cudaFuncAttributeMaxDynamicSharedMemorySize,
                             SMEM_TOTAL);
        attr_set = true;
    }

    init_kernel<<<1, 32>>>(out);
    prep_kernel<<<BB * NN / 256, 256>>>(points, f1, f2, out);
    ce_kernel<<<dim3(NN / ROWS, BB), THREADS, SMEM_TOTAL>>>(points, w, out);
}

// round 5
// speedup vs baseline: 5.0338x; 1.7029x over previous
#include <cuda_runtime.h>
#include <cuda_fp16.h>
#include <math.h>
#include <stdint.h>

#define BB 4
#define NN 4096
#define DD 64
#define SHIFT 64.0f
#define L2E 1.4426950408889634f
#define LN2 0.6931471805599453f
#define TWO_L2E (2.0f * L2E)
#define NGL2E (-40000.0f * L2E)       /* -(1/sigma^2)*log2(e) */
#define STH 0.00226f                  /* dist^2 beyond which exp underflows to 0 */

#define ROWS 128
#define CT 128
#define T_TILES (NN / CT)             /* 32 */
#define THREADS 512

/* ---- SMEM layout (bytes) ---- */
#define OFF_A    0                    /* 16384 */
#define OFF_B    16384                /* 2 x 16384 */
#define OFF_COLC 49152                /* 2 x 2048 */
#define OFF_RED  53248                /* 3*128 floats = 1536 */
#define OFF_WSUM 54784                /* 16 floats */
#define SMEM_TOTAL 54912

/* ---- device scratch (blocked, swizzled fp16 tiles) ---- */
__device__ __align__(16) unsigned char g_f1h[BB * NN * 128];
__device__ __align__(16) unsigned char g_f2h[BB * NN * 128];
__device__ float g_colc[BB * T_TILES * 4 * 128];  /* x,y,z,colk SoA per tile */
__device__ float g_rowk[BB * NN];                 /* L2E*(SHIFT - n1) */

/* ------------------------------- asm helpers ----------------------------- */
__device__ __forceinline__ uint32_t smem_u32(const void* p) {
    uint32_t a;
    asm("{ .reg .u64 t; cvta.to.shared.u64 t, %1; cvt.u32.u64 %0, t; }" : "=r"(a) : "l"(p));
    return a;
}
__device__ __forceinline__ float ex2_(float x) {
    float r;
    asm("ex2.approx.ftz.f32 %0, %1;" : "=f"(r) : "f"(x));
    return r;
}
#define CPA16(dst, src) \
    asm volatile("cp.async.cg.shared.global [%0], [%1], 16;" :: "r"(dst), "l"(src))
#define CPA_COMMIT() asm volatile("cp.async.commit_group;" ::: "memory")
#define CPA_WAIT0()  asm volatile("cp.async.wait_group 0;" ::: "memory")

#define LDSM4(r, addr) \
    asm volatile("ldmatrix.sync.aligned.m8n8.x4.shared.b16 {%0,%1,%2,%3}, [%4];" \
        : "=r"((r)[0]), "=r"((r)[1]), "=r"((r)[2]), "=r"((r)[3]) : "r"(addr))

#define MMA16816(c, a, b0_, b1_) \
    asm volatile("mma.sync.aligned.m16n8k16.row.col.f32.f16.f16.f32 " \
        "{%0,%1,%2,%3},{%4,%5,%6,%7},{%8,%9},{%0,%1,%2,%3};" \
        : "+f"((c)[0]), "+f"((c)[1]), "+f"((c)[2]), "+f"((c)[3]) \
        : "r"((a)[0]), "r"((a)[1]), "r"((a)[2]), "r"((a)[3]), "r"(b0_), "r"(b1_))

/* ------------------------------- prep kernel ----------------------------- */
__device__ __forceinline__ uint4 cvt8h(const float* f) {
    uint32_t h[4];
#pragma unroll
    for (int i = 0; i < 4; i++) {
        __half2 hh = __floats2half2_rn(f[2 * i], f[2 * i + 1]);
        h[i] = *reinterpret_cast<uint32_t*>(&hh);
    }
    return make_uint4(h[0], h[1], h[2], h[3]);
}

__global__ void __launch_bounds__(256)
prep_kernel(const float* __restrict__ points,
            const float* __restrict__ f1,
            const float* __restrict__ f2,
            float* __restrict__ out)
{
    __shared__ float wsum[8];
    const int tid = threadIdx.x;
    const int row = blockIdx.x * 256 + tid;        /* 0 .. B*NN-1 */
    const int b = row >> 12, n = row & (NN - 1);
    const int t = n >> 7, rin = n & 127;
    const size_t tb = ((size_t)(b * T_TILES + t)) * 16384 + (size_t)rin * 128;
    const int sw = rin & 7;

    float f[DD];
    float n1 = 0.f, n2 = 0.f;
    {
        const float4* v = (const float4*)(f1 + (size_t)row * DD);
#pragma unroll
        for (int j = 0; j < DD / 4; j++) {
            float4 x = v[j];
            f[4 * j] = x.x; f[4 * j + 1] = x.y; f[4 * j + 2] = x.z; f[4 * j + 3] = x.w;
            n1 = fmaf(x.x, x.x, n1); n1 = fmaf(x.y, x.y, n1);
            n1 = fmaf(x.z, x.z, n1); n1 = fmaf(x.w, x.w, n1);
        }
#pragma unroll
        for (int c = 0; c < 8; c++)
            *reinterpret_cast<uint4*>(g_f1h + tb + (size_t)(((c ^ sw) << 4))) = cvt8h(f + 8 * c);
    }
    {
        const float4* v = (const float4*)(f2 + (size_t)row * DD);
#pragma unroll
        for (int j = 0; j < DD / 4; j++) {
            float4 x = v[j];
            f[4 * j] = x.x; f[4 * j + 1] = x.y; f[4 * j + 2] = x.z; f[4 * j + 3] = x.w;
            n2 = fmaf(x.x, x.x, n2); n2 = fmaf(x.y, x.y, n2);
            n2 = fmaf(x.z, x.z, n2); n2 = fmaf(x.w, x.w, n2);
        }
#pragma unroll
        for (int c = 0; c < 8; c++)
            *reinterpret_cast<uint4*>(g_f2h + tb + (size_t)(((c ^ sw) << 4))) = cvt8h(f + 8 * c);
    }
    g_rowk[row] = L2E * (SHIFT - n1);
    const int cbase = (b * T_TILES + t) * 512;
    g_colc[cbase + rin]       = points[(size_t)row * 3 + 0];
    g_colc[cbase + 128 + rin] = points[(size_t)row * 3 + 1];
    g_colc[cbase + 256 + rin] = points[(size_t)row * 3 + 2];
    g_colc[cbase + 384 + rin] = -L2E * n2;

    /* reg loss */
    float s = n1 + n2;
#pragma unroll
    for (int o = 16; o > 0; o >>= 1) s += __shfl_down_sync(0xffffffffu, s, o);
    if ((tid & 31) == 0) wsum[tid >> 5] = s;
    __syncthreads();
    if (tid < 8) {
        float v = wsum[tid];
        v += __shfl_down_sync(0xffu, v, 4);
        v += __shfl_down_sync(0xffu, v, 2);
        v += __shfl_down_sync(0xffu, v, 1);
        if (tid == 0) atomicAdd(&out[4 + b], v * (1.0f / (float)(NN * DD)));
    }
}

__global__ void init_kernel(float* out) {
    if (threadIdx.x < 8) out[threadIdx.x] = 0.0f;
}

/* ----------------------------- epilogue helper --------------------------- */
__device__ __forceinline__ void row_epi(
    float d0, float d1, float d2, float d3,
    const float* qxv, const float* qyv, const float* qzv, const float* kv,
    float px, float py, float pz, float rowk,
    float& zpd, float& tpd, float& zfd)
{
    float dv[4] = { d0, d1, d2, d3 };
    float za[4], sv[4];
    float smin = 1e30f;
#pragma unroll
    for (int c = 0; c < 4; c++) {
        float dx = qxv[c] - px, dy = qyv[c] - py, dz = qzv[c] - pz;
        float s = fmaf(dx, dx, fmaf(dy, dy, dz * dz));
        sv[c] = s;
        smin = fminf(smin, s);
        float zarg = fmaf(dv[c], TWO_L2E, rowk + kv[c]);  /* = L2E*(fd+SHIFT) */
        za[c] = zarg;
        zfd += ex2_(zarg);
    }
    if (smin < STH) {
#pragma unroll
        for (int c = 0; c < 4; c++) {
            float e = ex2_(sv[c] * NGL2E);
            zpd += e;
            float fd = fmaf(za[c], LN2, -SHIFT);
            tpd = fmaf(e, fd, tpd);
        }
    }
}

/* -------------------------------- ce kernel ------------------------------ */
__global__ void __launch_bounds__(THREADS, 1)
ce_kernel(const float* __restrict__ w, float* __restrict__ out)
{
    extern __shared__ char sm[];
    const uint32_t smb = smem_u32(sm);
    const int tid = threadIdx.x;
    const int wid = tid >> 5, lane = tid & 31;
    const int rg = wid & 7;          /* row group: rows rg*16..  */
    const int ch = wid >> 3;         /* column half: cols ch*64.. */
    const int b = blockIdx.y, bx = blockIdx.x;

    /* ---- prologue cp.async: A tile + B tile 0 + colc 0 ---- */
    {
        const size_t abase = ((size_t)(b * T_TILES + bx)) * 16384;
        const size_t bbase = ((size_t)(b * T_TILES + 0)) * 16384;
#pragma unroll
        for (int j = 0; j < 2; j++) {
            const uint32_t c16 = (uint32_t)(tid + j * 512) * 16;
            CPA16(smb + OFF_A + c16, g_f1h + abase + c16);
            CPA16(smb + OFF_B + c16, g_f2h + bbase + c16);
        }
        if (tid < 128) {
            const uint32_t c16 = (uint32_t)tid * 16;
            CPA16(smb + OFF_COLC + c16,
                  (const char*)(g_colc + (size_t)(b * T_TILES) * 512) + c16);
        }
        CPA_COMMIT();
    }

    /* ---- per-thread row constants (rows r0, r0+8 of this CTA's tile) ---- */
    const int q = lane & 3;
    const int kq = lane >> 2;
    const int r0 = rg * 16 + kq;
    const int n0 = bx * ROWS + r0;
    const float rowka = g_rowk[b * NN + n0];
    const float rowkb = g_rowk[b * NN + n0 + 8];
    const float* myc = g_colc + (size_t)(b * T_TILES + bx) * 512;
    const float pxa = myc[r0],       pya = myc[128 + r0],     pza = myc[256 + r0];
    const float pxb = myc[r0 + 8],   pyb = myc[128 + r0 + 8], pzb = myc[256 + r0 + 8];

    CPA_WAIT0();
    __syncthreads();

    /* ---- persistent A fragments ---- */
    const int g = lane >> 3, li = lane & 7, gh = g >> 1;
    uint32_t af[4][4];
    {
        const int rA = rg * 16 + (g & 1) * 8 + li;
        const uint32_t ab = smb + OFF_A + rA * 128;
        const int sA = rA & 7;
#pragma unroll
        for (int kc = 0; kc < 4; kc++)
            LDSM4(af[kc], ab + (uint32_t)(((2 * kc + gh) ^ sA) << 4));
    }
    const int rl = (g & 1) * 8 + li;   /* row within a 16-col group of B */
    const int sB = rl & 7;

    float zpd0 = 0.f, tpd0 = 0.f, zfd0 = 0.f;
    float zpd1 = 0.f, tpd1 = 0.f, zfd1 = 0.f;

    for (int t = 0; t < T_TILES; t++) {
        const int bf = t & 1;
        if (t + 1 < T_TILES) {
            const int nbf = bf ^ 1;
            const size_t bbase = ((size_t)(b * T_TILES + t + 1)) * 16384;
            const uint32_t dstB = smb + OFF_B + nbf * 16384;
#pragma unroll
            for (int j = 0; j < 2; j++) {
                const uint32_t c16 = (uint32_t)(tid + j * 512) * 16;
                CPA16(dstB + c16, g_f2h + bbase + c16);
            }
            if (tid < 128) {
                const uint32_t c16 = (uint32_t)tid * 16;
                CPA16(smb + OFF_COLC + nbf * 2048 + c16,
                      (const char*)(g_colc + (size_t)(b * T_TILES + t + 1) * 512) + c16);
            }
            CPA_COMMIT();
        }

        const float* colcp = (const float*)(sm + OFF_COLC + bf * 2048);
        const uint32_t bbuf = smb + OFF_B + bf * 16384;

#pragma unroll
        for (int cpl = 0; cpl < 4; cpl++) {
            const int cpg = ch * 4 + cpl;          /* 16-col group index */
            uint32_t bfrag[4][4];
            const uint32_t bb = bbuf + cpg * 2048 + rl * 128;
#pragma unroll
            for (int kc = 0; kc < 4; kc++)
                LDSM4(bfrag[kc], bb + (uint32_t)(((2 * kc + gh) ^ sB) << 4));

            float accA[4] = {0.f, 0.f, 0.f, 0.f};
            float accB[4] = {0.f, 0.f, 0.f, 0.f};
#pragma unroll
            for (int kc = 0; kc < 4; kc++) {
                MMA16816(accA, af[kc], bfrag[kc][0], bfrag[kc][2]);
                MMA16816(accB, af[kc], bfrag[kc][1], bfrag[kc][3]);
            }

            const int lc0 = cpg * 16 + 2 * q;
            const int lc1 = lc0 + 8;
            float2 x0 = *(const float2*)(colcp + lc0);
            float2 x1 = *(const float2*)(colcp + lc1);
            float2 y0 = *(const float2*)(colcp + 128 + lc0);
            float2 y1 = *(const float2*)(colcp + 128 + lc1);
            float2 z0 = *(const float2*)(colcp + 256 + lc0);
            float2 z1 = *(const float2*)(colcp + 256 + lc1);
            float2 k0 = *(const float2*)(colcp + 384 + lc0);
            float2 k1 = *(const float2*)(colcp + 384 + lc1);
            const float qxv[4] = { x0.x, x0.y, x1.x, x1.y };
            const float qyv[4] = { y0.x, y0.y, y1.x, y1.y };
            const float qzv[4] = { z0.x, z0.y, z1.x, z1.y };
            const float kv[4]  = { k0.x, k0.y, k1.x, k1.y };

            row_epi(accA[0], accA[1], accB[0], accB[1],
                    qxv, qyv, qzv, kv, pxa, pya, pza, rowka, zpd0, tpd0, zfd0);
            row_epi(accA[2], accA[3], accB[2], accB[3],
                    qxv, qyv, qzv, kv, pxb, pyb, pzb, rowkb, zpd1, tpd1, zfd1);
        }

        if (t + 1 < T_TILES) CPA_WAIT0();
        __syncthreads();
    }

    /* ---- reduce over the 4 quad lanes (columns within fragment) ---- */
#pragma unroll
    for (int o = 1; o <= 2; o <<= 1) {
        zpd0 += __shfl_xor_sync(0xffffffffu, zpd0, o);
        tpd0 += __shfl_xor_sync(0xffffffffu, tpd0, o);
        zfd0 += __shfl_xor_sync(0xffffffffu, zfd0, o);
        zpd1 += __shfl_xor_sync(0xffffffffu, zpd1, o);
        tpd1 += __shfl_xor_sync(0xffffffffu, tpd1, o);
        zfd1 += __shfl_xor_sync(0xffffffffu, zfd1, o);
    }
    /* ---- combine the two column halves via smem ---- */
    float* red = (float*)(sm + OFF_RED);
    if (ch == 1 && q == 0) {
        red[r0] = zpd0;           red[r0 + 8] = zpd1;
        red[128 + r0] = tpd0;     red[128 + r0 + 8] = tpd1;
        red[256 + r0] = zfd0;     red[256 + r0 + 8] = zfd1;
    }
    __syncthreads();
    float val = 0.f;
    if (ch == 0 && q == 0) {
        float ZP0 = zpd0 + red[r0],       TP0 = tpd0 + red[128 + r0],     ZF0 = zfd0 + red[256 + r0];
        float ZP1 = zpd1 + red[r0 + 8],   TP1 = tpd1 + red[128 + r0 + 8], ZF1 = zfd1 + red[256 + r0 + 8];
        float ce0 = (logf(ZF0) - SHIFT) - TP0 / ZP0;
        float ce1 = (logf(ZF1) - SHIFT) - TP1 / ZP1;
        val = w[b * NN + n0] * ce0 + w[b * NN + n0 + 8] * ce1;
    }
#pragma unroll
    for (int o = 16; o >= 4; o >>= 1) val += __shfl_down_sync(0xffffffffu, val, o);
    float* wsum = (float*)(sm + OFF_WSUM);
    if (lane == 0) wsum[wid] = val;
    __syncthreads();
    if (tid < 8) {                               /* only warps 0-7 (ch==0) contribute */
        float v = wsum[tid];
        v += __shfl_down_sync(0xffu, v, 4);
        v += __shfl_down_sync(0xffu, v, 2);
        v += __shfl_down_sync(0xffu, v, 1);
        if (tid == 0) atomicAdd(&out[b], v);
    }
}

/* -------------------------------- launcher ------------------------------- */
extern "C" void kernel_launch(void* const* d_in, const int* in_sizes, int n_in,
                              void* d_out, int out_size)
{
    const float* points = (const float*)d_in[0];
    const float* f1     = (const float*)d_in[1];
    const float* f2     = (const float*)d_in[2];
    const float* w      = (const float*)d_in[3];
    float* out          = (float*)d_out;

    static bool attr_set = false;
    if (!attr_set) {
        cudaFuncSetAttribute(ce_kernel, cudaFuncAttributeMaxDynamicSharedMemorySize,
                             SMEM_TOTAL);
        attr_set = true;
    }

    init_kernel<<<1, 32>>>(out);
    prep_kernel<<<BB * NN / 256, 256>>>(points, f1, f2, out);
    ce_kernel<<<dim3(NN / ROWS, BB), THREADS, SMEM_TOTAL>>>(w, out);
}